// round 3
// baseline (speedup 1.0000x reference)
#include <cuda_runtime.h>
#include <cstdint>

typedef unsigned long long ULL;

#define NTOK 1024
#define CQ   768
#define CZ   128
#define NH   16
#define HD   48
#define HDQ  768   // NH*HD
#define QSCALE 0.14433756729740643f  // 1/sqrt(48)

// ---------------- f32x2 packed helpers ----------------
__device__ __forceinline__ ULL fma2(ULL a, ULL b, ULL c) {
    ULL d; asm("fma.rn.f32x2 %0, %1, %2, %3;" : "=l"(d) : "l"(a), "l"(b), "l"(c)); return d;
}
__device__ __forceinline__ ULL add2(ULL a, ULL b) {
    ULL d; asm("add.rn.f32x2 %0, %1, %2;" : "=l"(d) : "l"(a), "l"(b)); return d;
}
__device__ __forceinline__ ULL pack2(float lo, float hi) {
    ULL d; asm("mov.b64 %0, {%1, %2};" : "=l"(d) : "f"(lo), "f"(hi)); return d;
}
__device__ __forceinline__ float lo2(ULL u){ return __uint_as_float((unsigned)u); }
__device__ __forceinline__ float hi2(ULL u){ return __uint_as_float((unsigned)(u >> 32)); }

// ---------------- scratch ----------------
__device__ float g_an[NTOK * CQ];
__device__ float g_bias[(size_t)NH * NTOK * NTOK];   // pair bias -> raw scores (in place)
__device__ float g_q[NH * NTOK * HD];
__device__ float g_kT[NH * HD * NTOK];
__device__ float g_v[NH * NTOK * HD];
__device__ float g_gate[NTOK * HDQ];
__device__ float g_og[NTOK * HDQ];
__device__ float2 g_stats[NH * NTOK];                // (rowmax, rowsumexp)

// ---------------- LayerNorm of a ----------------
__global__ void k_ln_a(const float* __restrict__ a, const float* __restrict__ g,
                       const float* __restrict__ b) {
    int row = blockIdx.x, tid = threadIdx.x;
    const float* x = a + (size_t)row * CQ;
    float v0 = x[tid], v1 = x[tid + 256], v2 = x[tid + 512];
    float s = v0 + v1 + v2;
    float ss = v0*v0 + v1*v1 + v2*v2;
    __shared__ float sm[8], sm2[8];
    #pragma unroll
    for (int o = 16; o; o >>= 1) {
        s  += __shfl_xor_sync(0xffffffffu, s, o);
        ss += __shfl_xor_sync(0xffffffffu, ss, o);
    }
    if ((tid & 31) == 0) { sm[tid >> 5] = s; sm2[tid >> 5] = ss; }
    __syncthreads();
    if (tid == 0) {
        float S = 0, SS = 0;
        for (int i = 0; i < 8; i++) { S += sm[i]; SS += sm2[i]; }
        float mu = S * (1.0f / CQ);
        float var = SS * (1.0f / CQ) - mu * mu;
        sm[0] = mu; sm2[0] = rsqrtf(var + 1e-5f);
    }
    __syncthreads();
    float mu = sm[0], rstd = sm2[0];
    float* o = g_an + (size_t)row * CQ;
    o[tid]       = (v0 - mu) * rstd * g[tid]       + b[tid];
    o[tid + 256] = (v1 - mu) * rstd * g[tid + 256] + b[tid + 256];
    o[tid + 512] = (v2 - mu) * rstd * g[tid + 512] + b[tid + 512];
}

// ---------------- pair bias (unchanged from R2) ----------------
#define PB_SMEM_FLOATS (2*256*32 + 2048 + 32)
__global__ __launch_bounds__(256, 2)
void k_pair_bias(const float* __restrict__ z, const float* __restrict__ gz,
                 const float* __restrict__ bz, const float* __restrict__ wz) {
    extern __shared__ float sm[];
    float* zb    = sm;
    float* wps   = sm + 16384;
    float* cs_cb = wps + 2048;

    int tid = threadIdx.x;
    for (int i = tid; i < CZ * NH; i += 256) {
        int c = i >> 4, h = i & 15;
        wps[(c >> 1) * 32 + h * 2 + (c & 1)] = gz[c] * wz[c * NH + h];
    }
    __syncthreads();
    if (tid < 16) {
        float cs = 0.f, cb = 0.f;
        for (int c = 0; c < CZ; c++) {
            cs += wps[(c >> 1) * 32 + tid * 2 + (c & 1)];
            cb += bz[c] * wz[c * NH + tid];
        }
        cs_cb[tid] = cs; cs_cb[16 + tid] = cb;
    }
    __syncthreads();

    int tile = blockIdx.x;
    const float4* zg = (const float4*)(z + (size_t)tile * 256 * CZ);

    int srow[8], sf[8];
    #pragma unroll
    for (int j = 0; j < 8; j++) { int i = tid + j * 256; srow[j] = i >> 3; sf[j] = i & 7; }

    float4 pre[8];
    #pragma unroll
    for (int j = 0; j < 8; j++)
        pre[j] = zg[(size_t)srow[j] * 32 + sf[j]];

    ULL acc[NH];
    #pragma unroll
    for (int h = 0; h < NH; h++) acc[h] = 0ULL;
    ULL sum2 = 0ULL, ss2 = 0ULL;

    for (int c = 0; c < 4; c++) {
        float* buf = zb + (c & 1) * 8192;
        #pragma unroll
        for (int j = 0; j < 8; j++)
            *(float4*)(buf + srow[j] * 32 + ((sf[j] + srow[j]) & 7) * 4) = pre[j];
        __syncthreads();
        if (c < 3) {
            #pragma unroll
            for (int j = 0; j < 8; j++)
                pre[j] = zg[(size_t)srow[j] * 32 + (c + 1) * 8 + sf[j]];
        }
        #pragma unroll
        for (int j = 0; j < 8; j++) {
            int pos = (j + tid) & 7;
            float4 zv = *(const float4*)(buf + tid * 32 + pos * 4);
            ULL z01 = ((const ULL*)&zv)[0];
            ULL z23 = ((const ULL*)&zv)[1];
            sum2 = add2(sum2, add2(z01, z23));
            ss2  = fma2(z01, z01, fma2(z23, z23, ss2));
            int p0 = c * 16 + 2 * j;
            const float4* w0 = (const float4*)(wps + p0 * 32);
            const float4* w1 = (const float4*)(wps + p0 * 32 + 32);
            #pragma unroll
            for (int h2 = 0; h2 < 8; h2++) {
                float4 wa = w0[h2];
                float4 wb = w1[h2];
                acc[2*h2]     = fma2(z01, ((const ULL*)&wa)[0], acc[2*h2]);
                acc[2*h2 + 1] = fma2(z01, ((const ULL*)&wa)[1], acc[2*h2 + 1]);
                acc[2*h2]     = fma2(z23, ((const ULL*)&wb)[0], acc[2*h2]);
                acc[2*h2 + 1] = fma2(z23, ((const ULL*)&wb)[1], acc[2*h2 + 1]);
            }
        }
        __syncthreads();
    }

    float sum = lo2(sum2) + hi2(sum2);
    float ss  = lo2(ss2)  + hi2(ss2);
    float mu  = sum * (1.0f / CZ);
    float var = ss * (1.0f / CZ) - mu * mu;
    float rstd = rsqrtf(var + 1e-5f);

    float* outs = zb;
    #pragma unroll
    for (int h = 0; h < NH; h++) {
        float d = lo2(acc[h]) + hi2(acc[h]);
        outs[h * 256 + tid] = rstd * (d - mu * cs_cb[h]) + cs_cb[16 + h];
    }
    __syncthreads();
    #pragma unroll
    for (int it = 0; it < 4; it++) {
        int idx = tid + it * 256;
        int h = idx >> 6, j4 = idx & 63;
        float4 v = *(const float4*)(outs + h * 256 + j4 * 4);
        *(float4*)(g_bias + ((size_t)h << 20) + (size_t)tile * 256 + j4 * 4) = v;
    }
}

// ---------------- SGEMM 64x128 tile, 4x8 per thread, k-chunk 32, reg prefetch ----------------
#define SA_STR 36
#define SB_STR 132
__device__ __forceinline__ void sgemm64x128(
    const float* __restrict__ A, const float* __restrict__ B,
    int K, int ldA, int ldB, int row0, int col0,
    float* sA, float* sB, ULL acc[4][4])
{
    int tid = threadIdx.x;
    int tm = (tid >> 4) << 2;     // 4 rows
    int tn8 = (tid & 15) << 3;    // 8 cols
    #pragma unroll
    for (int i = 0; i < 4; i++)
        #pragma unroll
        for (int j = 0; j < 4; j++) acc[i][j] = 0ULL;

    int ar[2], akq[2], br[4], bn[4];
    #pragma unroll
    for (int j = 0; j < 2; j++) { int fi = tid + j * 256; ar[j] = fi >> 3; akq[j] = fi & 7; }
    #pragma unroll
    for (int j = 0; j < 4; j++) { int fi = tid + j * 256; br[j] = fi >> 5; bn[j] = fi & 31; }

    float4 pa[2], pb[4];
    #pragma unroll
    for (int j = 0; j < 2; j++)
        pa[j] = *(const float4*)(A + (size_t)(row0 + ar[j]) * ldA + akq[j] * 4);
    #pragma unroll
    for (int j = 0; j < 4; j++)
        pb[j] = *(const float4*)(B + (size_t)br[j] * ldB + col0 + bn[j] * 4);

    for (int k0 = 0; k0 < K; k0 += 32) {
        #pragma unroll
        for (int j = 0; j < 2; j++)
            *(float4*)(sA + ar[j] * SA_STR + akq[j] * 4) = pa[j];
        #pragma unroll
        for (int j = 0; j < 4; j++)
            *(float4*)(sB + br[j] * SB_STR + bn[j] * 4) = pb[j];
        __syncthreads();
        if (k0 + 32 < K) {
            #pragma unroll
            for (int j = 0; j < 2; j++)
                pa[j] = *(const float4*)(A + (size_t)(row0 + ar[j]) * ldA + k0 + 32 + akq[j] * 4);
            #pragma unroll
            for (int j = 0; j < 4; j++)
                pb[j] = *(const float4*)(B + (size_t)(k0 + 32 + br[j]) * ldB + col0 + bn[j] * 4);
        }
        #pragma unroll 8
        for (int kk = 0; kk < 32; kk++) {
            float4 b0 = *(const float4*)(sB + kk * SB_STR + tn8);
            float4 b1 = *(const float4*)(sB + kk * SB_STR + tn8 + 4);
            ULL bl0 = ((const ULL*)&b0)[0], bh0 = ((const ULL*)&b0)[1];
            ULL bl1 = ((const ULL*)&b1)[0], bh1 = ((const ULL*)&b1)[1];
            #pragma unroll
            for (int i = 0; i < 4; i++) {
                float a = sA[(tm + i) * SA_STR + kk];
                ULL a2 = pack2(a, a);
                acc[i][0] = fma2(a2, bl0, acc[i][0]);
                acc[i][1] = fma2(a2, bh0, acc[i][1]);
                acc[i][2] = fma2(a2, bl1, acc[i][2]);
                acc[i][3] = fma2(a2, bh1, acc[i][3]);
            }
        }
        __syncthreads();
    }
}

// ---------------- QKVG projections ----------------
__global__ __launch_bounds__(256)
void k_qkvg(const float* __restrict__ wq, const float* __restrict__ wk,
            const float* __restrict__ wv, const float* __restrict__ wg,
            const float* __restrict__ bg) {
    __shared__ float sA[64 * SA_STR], sB[32 * SB_STR];
    ULL acc[4][4];
    int mode = blockIdx.z;
    const float* B = (mode == 0) ? wq : (mode == 1) ? wk : (mode == 2) ? wv : wg;
    int row0 = blockIdx.y * 64, col0 = blockIdx.x * 128;
    sgemm64x128(g_an, B, CQ, CQ, HDQ, row0, col0, sA, sB, acc);

    int tid = threadIdx.x;
    int tm = (tid >> 4) << 2, tn8 = (tid & 15) << 3;
    #pragma unroll
    for (int i = 0; i < 4; i++) {
        int row = row0 + tm + i;
        #pragma unroll
        for (int j = 0; j < 8; j++) {
            int col = col0 + tn8 + j;
            float v = (j & 1) ? hi2(acc[i][j >> 1]) : lo2(acc[i][j >> 1]);
            int h = col / HD, d = col - h * HD;
            if (mode == 0)      g_q [((size_t)h * NTOK + row) * HD + d] = v * QSCALE;
            else if (mode == 1) g_kT[((size_t)h * HD + d) * NTOK + row] = v;
            else if (mode == 2) g_v [((size_t)h * NTOK + row) * HD + d] = v;
            else                g_gate[(size_t)row * HDQ + col] = 1.f / (1.f + __expf(-(v + bg[col])));
        }
    }
}

// ---------------- pass A: S = QK^T + bias + mask (in place over g_bias) + row stats ----------------
#define SQ_STR  52
#define SKT_STR 132
__global__ __launch_bounds__(256)
void k_scoresB(const float* __restrict__ mask) {
    __shared__ float sQ[64 * SQ_STR];
    __shared__ float sKT[48 * SKT_STR];
    __shared__ float smr[64];

    int h = blockIdx.y, qt = blockIdx.x, tid = threadIdx.x;
    int row0 = qt * 64;

    const float* Q = g_q + ((size_t)h * NTOK + row0) * HD;
    for (int fi = tid; fi < 64 * 12; fi += 256) {
        int r = fi / 12, c4 = fi - r * 12;
        float4 v = *(const float4*)(Q + r * HD + c4 * 4);
        *(float4*)(sQ + r * SQ_STR + c4 * 4) = v;
    }
    if (tid < 64) smr[tid] = mask[row0 + tid];

    int tm = (tid >> 4) << 2, tn8 = (tid & 15) << 3;
    float m_i[4], s_i[4];
    #pragma unroll
    for (int i = 0; i < 4; i++) { m_i[i] = -1e30f; s_i[i] = 0.f; }

    float* biasBase = g_bias + ((size_t)h << 20);

    for (int cc = 0; cc < 8; cc++) {
        int c0 = cc * 128;
        __syncthreads();
        for (int fi = tid; fi < 48 * 32; fi += 256) {
            int d = fi >> 5, c8 = fi & 31;
            float4 v = *(const float4*)(g_kT + ((size_t)h * HD + d) * NTOK + c0 + c8 * 4);
            *(float4*)(sKT + d * SKT_STR + c8 * 4) = v;
        }
        __syncthreads();

        ULL acc[4][4];
        #pragma unroll
        for (int i = 0; i < 4; i++)
            #pragma unroll
            for (int j = 0; j < 4; j++) acc[i][j] = 0ULL;

        #pragma unroll 8
        for (int kk = 0; kk < HD; kk++) {
            float4 b0 = *(const float4*)(sKT + kk * SKT_STR + tn8);
            float4 b1 = *(const float4*)(sKT + kk * SKT_STR + tn8 + 4);
            ULL bl0 = ((const ULL*)&b0)[0], bh0 = ((const ULL*)&b0)[1];
            ULL bl1 = ((const ULL*)&b1)[0], bh1 = ((const ULL*)&b1)[1];
            #pragma unroll
            for (int i = 0; i < 4; i++) {
                float a = sQ[(tm + i) * SQ_STR + kk];
                ULL a2 = pack2(a, a);
                acc[i][0] = fma2(a2, bl0, acc[i][0]);
                acc[i][1] = fma2(a2, bh0, acc[i][1]);
                acc[i][2] = fma2(a2, bl1, acc[i][2]);
                acc[i][3] = fma2(a2, bh1, acc[i][3]);
            }
        }

        float4 mc0 = *(const float4*)(mask + c0 + tn8);
        float4 mc1 = *(const float4*)(mask + c0 + tn8 + 4);
        #pragma unroll
        for (int i = 0; i < 4; i++) {
            int grow = row0 + tm + i;
            float mr = smr[tm + i];
            float4* bp = (float4*)(biasBase + (size_t)grow * NTOK + c0 + tn8);
            float4 bv0 = bp[0], bv1 = bp[1];
            float4 v0, v1;
            v0.x = lo2(acc[i][0]) + bv0.x + 1e9f * (mr * mc0.x - 1.f);
            v0.y = hi2(acc[i][0]) + bv0.y + 1e9f * (mr * mc0.y - 1.f);
            v0.z = lo2(acc[i][1]) + bv0.z + 1e9f * (mr * mc0.z - 1.f);
            v0.w = hi2(acc[i][1]) + bv0.w + 1e9f * (mr * mc0.w - 1.f);
            v1.x = lo2(acc[i][2]) + bv1.x + 1e9f * (mr * mc1.x - 1.f);
            v1.y = hi2(acc[i][2]) + bv1.y + 1e9f * (mr * mc1.y - 1.f);
            v1.z = lo2(acc[i][3]) + bv1.z + 1e9f * (mr * mc1.z - 1.f);
            v1.w = hi2(acc[i][3]) + bv1.w + 1e9f * (mr * mc1.w - 1.f);
            bp[0] = v0; bp[1] = v1;
            float vm = fmaxf(fmaxf(fmaxf(v0.x, v0.y), fmaxf(v0.z, v0.w)),
                             fmaxf(fmaxf(v1.x, v1.y), fmaxf(v1.z, v1.w)));
            float nm = fmaxf(m_i[i], vm);
            float sadd = __expf(v0.x - nm) + __expf(v0.y - nm) + __expf(v0.z - nm) + __expf(v0.w - nm)
                       + __expf(v1.x - nm) + __expf(v1.y - nm) + __expf(v1.z - nm) + __expf(v1.w - nm);
            s_i[i] = s_i[i] * __expf(m_i[i] - nm) + sadd;
            m_i[i] = nm;
        }
    }

    // reduce over the 16 col-lanes (same warp half)
    #pragma unroll
    for (int off = 8; off; off >>= 1) {
        #pragma unroll
        for (int i = 0; i < 4; i++) {
            float om = __shfl_xor_sync(0xffffffffu, m_i[i], off);
            float os = __shfl_xor_sync(0xffffffffu, s_i[i], off);
            float nm = fmaxf(m_i[i], om);
            s_i[i] = s_i[i] * __expf(m_i[i] - nm) + os * __expf(om - nm);
            m_i[i] = nm;
        }
    }
    if ((tid & 15) == 0) {
        #pragma unroll
        for (int i = 0; i < 4; i++) {
            int grow = row0 + tm + i;
            g_stats[(size_t)h * NTOK + grow] = make_float2(m_i[i], s_i[i]);
        }
    }
}

// ---------------- pass B: O = softmax(S) @ V, gated ----------------
#define SP_STR 68
#define SV_STR 68
__global__ __launch_bounds__(256)
void k_pvB() {
    __shared__ float sP[64 * SP_STR];
    __shared__ float sV[64 * SV_STR];
    __shared__ float sM[64], sI[64];

    int h = blockIdx.y, qt = blockIdx.x, tid = threadIdx.x;
    int row0 = qt * 64;

    if (tid < 64) {
        float2 st = g_stats[(size_t)h * NTOK + row0 + tid];
        sM[tid] = st.x; sI[tid] = 1.f / st.y;
    }

    int tm = (tid >> 4) << 2, tn = (tid & 15) << 2;
    ULL acc[4][2];
    #pragma unroll
    for (int i = 0; i < 4; i++) { acc[i][0] = 0ULL; acc[i][1] = 0ULL; }

    const float* Sb = g_bias + ((size_t)h << 20);
    const float* Vh = g_v + (size_t)h * NTOK * HD;

    for (int t = 0; t < 16; t++) {
        __syncthreads();
        // stage exp'd P tile
        #pragma unroll
        for (int j = 0; j < 4; j++) {
            int fi = tid + j * 256;
            int r = fi >> 4, c4 = fi & 15;
            float4 v = *(const float4*)(Sb + (size_t)(row0 + r) * NTOK + t * 64 + c4 * 4);
            float m = sM[r], inv = sI[r];
            v.x = __expf(v.x - m) * inv;
            v.y = __expf(v.y - m) * inv;
            v.z = __expf(v.z - m) * inv;
            v.w = __expf(v.w - m) * inv;
            *(float4*)(sP + r * SP_STR + c4 * 4) = v;
        }
        // stage V tile (pad d to 64 with zeros)
        #pragma unroll
        for (int j = 0; j < 3; j++) {
            int fi = tid + j * 256;
            int r = fi / 12, d4 = fi - r * 12;
            float4 v = *(const float4*)(Vh + (size_t)(t * 64 + r) * HD + d4 * 4);
            *(float4*)(sV + r * SV_STR + d4 * 4) = v;
        }
        { int r = tid >> 2, sg = tid & 3;
          *(float4*)(sV + r * SV_STR + 48 + sg * 4) = make_float4(0.f, 0.f, 0.f, 0.f); }
        __syncthreads();

        #pragma unroll 8
        for (int kk = 0; kk < 64; kk++) {
            float4 b = *(const float4*)(sV + kk * SV_STR + tn);
            ULL b01 = ((const ULL*)&b)[0], b23 = ((const ULL*)&b)[1];
            #pragma unroll
            for (int i = 0; i < 4; i++) {
                float a = sP[(tm + i) * SP_STR + kk];
                ULL a2 = pack2(a, a);
                acc[i][0] = fma2(a2, b01, acc[i][0]);
                acc[i][1] = fma2(a2, b23, acc[i][1]);
            }
        }
    }

    if (tn < HD) {
        #pragma unroll
        for (int i = 0; i < 4; i++) {
            int grow = row0 + tm + i;
            size_t idx = (size_t)grow * HDQ + h * HD + tn;
            float4 g4 = *(const float4*)(g_gate + idx);
            float4 o;
            o.x = lo2(acc[i][0]) * g4.x;
            o.y = hi2(acc[i][0]) * g4.y;
            o.z = lo2(acc[i][1]) * g4.z;
            o.w = hi2(acc[i][1]) * g4.w;
            *(float4*)(g_og + idx) = o;
        }
    }
}

// ---------------- final projection ----------------
__global__ __launch_bounds__(256)
void k_out(const float* __restrict__ wo, const float* __restrict__ bo,
           float* __restrict__ out) {
    __shared__ float sA[64 * SA_STR], sB[32 * SB_STR];
    ULL acc[4][4];
    int row0 = blockIdx.y * 64, col0 = blockIdx.x * 128;
    sgemm64x128(g_og, wo, CQ, CQ, CQ, row0, col0, sA, sB, acc);

    int tid = threadIdx.x;
    int tm = (tid >> 4) << 2, tn8 = (tid & 15) << 3;
    float4 bv0 = *(const float4*)(bo + col0 + tn8);
    float4 bv1 = *(const float4*)(bo + col0 + tn8 + 4);
    #pragma unroll
    for (int i = 0; i < 4; i++) {
        int row = row0 + tm + i;
        float4 r0, r1;
        r0.x = lo2(acc[i][0]) + bv0.x;
        r0.y = hi2(acc[i][0]) + bv0.y;
        r0.z = lo2(acc[i][1]) + bv0.z;
        r0.w = hi2(acc[i][1]) + bv0.w;
        r1.x = lo2(acc[i][2]) + bv1.x;
        r1.y = hi2(acc[i][2]) + bv1.y;
        r1.z = lo2(acc[i][3]) + bv1.z;
        r1.w = hi2(acc[i][3]) + bv1.w;
        *(float4*)(out + (size_t)row * CQ + col0 + tn8)     = r0;
        *(float4*)(out + (size_t)row * CQ + col0 + tn8 + 4) = r1;
    }
}

// ---------------- launch ----------------
extern "C" void kernel_launch(void* const* d_in, const int* in_sizes, int n_in,
                              void* d_out, int out_size) {
    const float* a    = (const float*)d_in[0];
    const float* z    = (const float*)d_in[1];
    const float* mask = (const float*)d_in[2];
    const float* ga   = (const float*)d_in[3];
    const float* ba   = (const float*)d_in[4];
    const float* gz   = (const float*)d_in[5];
    const float* bz   = (const float*)d_in[6];
    const float* wz   = (const float*)d_in[7];
    const float* wq   = (const float*)d_in[8];
    const float* wk   = (const float*)d_in[9];
    const float* wv   = (const float*)d_in[10];
    const float* wg   = (const float*)d_in[11];
    const float* bg   = (const float*)d_in[12];
    const float* wo   = (const float*)d_in[13];
    const float* bo   = (const float*)d_in[14];
    float* out = (float*)d_out;

    cudaFuncSetAttribute(k_pair_bias, cudaFuncAttributeMaxDynamicSharedMemorySize,
                         PB_SMEM_FLOATS * 4);

    k_pair_bias<<<4096, 256, PB_SMEM_FLOATS * 4>>>(z, gz, bz, wz);
    k_ln_a<<<1024, 256>>>(a, ga, ba);
    k_qkvg<<<dim3(6, 16, 4), 256>>>(wq, wk, wv, wg, bg);
    k_scoresB<<<dim3(16, NH), 256>>>(mask);
    k_pvB<<<dim3(16, NH), 256>>>();
    k_out<<<dim3(6, 16), 256>>>(wo, bo, out);
}